// round 16
// baseline (speedup 1.0000x reference)
#include <cuda_runtime.h>

// XY model log-density: out[s] = sum_i cos(x[up(i)] - x[i]) + cos(x[right(i)] - x[i])
// 64x64 lattice (4096 sites), 16384 samples, BETA = 1.
//
// R16: R15 (chained chunks, pure MUFU, best 41.4us) + front-batched chain
// loads. The chain needs only 5 float4 (20 regs), so all 5 LDG.128 can issue
// before any MUFU work WITHOUT breaking the 32-reg / 8-CTA budget (unlike
// R4's 8-float4 attempt). MLP 2 -> 5 at unchanged occupancy.
//
// Thread t owns chunk chain {start, +16, +32, +48} (stride = one lattice
// row); each chunk's up-neighbor is the next chain chunk. 5 loads/thread.
// start = (tid>>4)*64 + (tid&15) keeps every warp LDG on 4x128B lines.

#define LATTICE 4096
#define THREADS 256

__global__ __launch_bounds__(THREADS) void xy_hamiltonian_kernel(
    const float* __restrict__ state,
    float* __restrict__ out)
{
    __shared__ float warp_sums[THREADS / 32];

    const int tid  = threadIdx.x;
    const int lane = tid & 31;
    const float4* __restrict__ rp4 =
        reinterpret_cast<const float4*>(state + (size_t)blockIdx.x * LATTICE);

    // Chain start: chunks with (m mod 64) < 16. Lanes 0-15 of a warp cover
    // 16 consecutive chunks of one lattice row; lanes 16-31 the next group.
    const int start = ((tid >> 4) << 6) + (tid & 15);

    // Right-neighbor source lane: within each 16-lane group, lane L's
    // boundary right-neighbor is lane L+1's c.x, wrapping at col 63.
    const int src_lane = (lane & ~15) | ((lane + 1) & 15);

    // ---- front-batched chain loads: 5 independent LDG.128 ----
    float4 c[5];
    #pragma unroll
    for (int j = 0; j < 5; j++)
        c[j] = __ldcs(&rp4[(start + 16 * j) & (LATTICE/4 - 1)]);

    float acc = 0.0f;
    #pragma unroll
    for (int j = 0; j < 4; j++) {
        const float4 cur = c[j];
        const float4 nxt = c[j + 1];
        const float xr3 = __shfl_sync(0xffffffffu, cur.x, src_lane);

        acc += __cosf(nxt.x - cur.x);   // up bonds
        acc += __cosf(nxt.y - cur.y);
        acc += __cosf(nxt.z - cur.z);
        acc += __cosf(nxt.w - cur.w);
        acc += __cosf(cur.y - cur.x);   // right bonds
        acc += __cosf(cur.z - cur.y);
        acc += __cosf(cur.w - cur.z);
        acc += __cosf(xr3   - cur.w);
    }

    // Warp reduce
    #pragma unroll
    for (int o = 16; o > 0; o >>= 1)
        acc += __shfl_down_sync(0xffffffffu, acc, o);
    if (lane == 0)
        warp_sums[tid >> 5] = acc;
    __syncthreads();

    // Final reduce across 8 warps
    if (tid < 8) {
        float v = warp_sums[tid];
        #pragma unroll
        for (int o = 4; o > 0; o >>= 1)
            v += __shfl_down_sync(0x000000ffu, v, o);
        if (tid == 0)
            out[blockIdx.x] = v;
    }
}

extern "C" void kernel_launch(void* const* d_in, const int* in_sizes, int n_in,
                              void* d_out, int out_size)
{
    const float* state = (const float*)d_in[0];
    // d_in[1] (shift table, int64) is reproduced arithmetically in-kernel.
    float* out = (float*)d_out;

    const int n_samples = in_sizes[0] / LATTICE;  // 16384
    xy_hamiltonian_kernel<<<n_samples, THREADS>>>(state, out);
}